// round 3
// baseline (speedup 1.0000x reference)
#include <cuda_runtime.h>
#include <cstddef>

// ---------------------------------------------------------------------------
// StokenAttention: B=8, C=256, H=W=128, 8x8 super-tokens -> 16x16 grid,
// NH=8 heads, HD=KD=32.
// Pipeline:
//   K1 pool      : stoken[b][t][c] = mean of 8x8 patch
//   K2 aff       : per token: aff = softmax_k(pix . stoken9) * C^-0.5,
//                  M[k][c] = sum_p pix[p][c]*aff[p][k], asum_tok[k]
//   K3 fold      : sf[b][n][c] = gather9(M) / (gather9(asum_tok)+1e-12)
//   K4 qkv gemm  : qkv[b][o][n] = w_qkv . sf
//   K5 attention : per (b,h,qchunk): online softmax + depthwise 3x3 PE
//   K6 proj gemm : sfa[b][n][o] = w_proj . tmp
//   K7 scatter   : out[c][s of token] = sum_k aff[c>>2][k]*sfa9[k][(c&3)*64+s]
//                  (reference's reshape reinterprets (p,C) flat as (C,SH,SW))
// ---------------------------------------------------------------------------

#define Bb 8
#define Cc 256
#define GG 16            // 16x16 token grid
#define NT 256           // tokens per batch
#define NP 64            // pixels per token
#define HW 16384         // 128*128
#define NH 8
#define HD 32

__device__ float g_stoken[Bb * NT * Cc];          // [b][t][c]
__device__ float g_aff[Bb * NT * NP * 9];         // [b][t][p][k]
__device__ float g_asum[Bb * NT * 9];             // [b][t][k]
__device__ float g_M[(size_t)Bb * NT * 9 * Cc];   // [b][t][k][c]
__device__ float g_sf[Bb * NT * Cc];              // [b][n][c]
__device__ float g_qkv[Bb * 768 * NT];            // [b][o][n]
__device__ float g_tmp[Bb * NT * Cc];             // [b][n][c]
__device__ float g_sfa[Bb * NT * Cc];             // [b][n][c]

#define AFF_SCALE 0.0625f                 // 256^-0.5
#define ATTN_SCALE 0.17677669529663687f   // 32^-0.5

// ------------------------------- K1: pooling -------------------------------
__global__ void k_pool(const float* __restrict__ x) {
    int bt = blockIdx.x;               // b*256 + t
    int t = bt & 255;
    int ty = t >> 4, tx = t & 15;
    int c = threadIdx.x;
    const float* xp = x + (size_t)(( (bt >> 8) * Cc + c)) * HW + (ty * 8) * 128 + tx * 8;
    float s = 0.f;
#pragma unroll
    for (int i = 0; i < 8; i++) {
        float4 a = *(const float4*)(xp + i * 128);
        float4 b4 = *(const float4*)(xp + i * 128 + 4);
        s += a.x + a.y + a.z + a.w + b4.x + b4.y + b4.z + b4.w;
    }
    g_stoken[bt * Cc + c] = s * (1.0f / 64.0f);
}

// ------------------------- K2: affinity + token GEMM ------------------------
// dyn smem: pix[64*257] | st9[9*256] | pd[4*64*9] | aff_s[64*9]
#define K2_PIX   (64 * 257)
#define K2_ST9   (9 * 256)
#define K2_PD    (4 * 64 * 9)
#define K2_AFFS  (64 * 9)
#define K2_SMEM  ((K2_PIX + K2_ST9 + K2_PD + K2_AFFS) * 4)

__global__ void k_aff(const float* __restrict__ x) {
    extern __shared__ float sm[];
    float* pix_s = sm;
    float* st9   = pix_s + K2_PIX;
    float* pd    = st9 + K2_ST9;
    float* aff_s = pd + K2_PD;

    int bt = blockIdx.x;
    int b = bt >> 8, t = bt & 255;
    int ty = t >> 4, tx = t & 15;
    int tid = threadIdx.x;

    // load 9 neighbor stoken vectors (zero outside grid)
    for (int idx = tid; idx < 9 * Cc; idx += 256) {
        int k = idx >> 8, c = idx & 255;
        int ny = ty + k / 3 - 1, nx = tx + k % 3 - 1;
        float v = 0.f;
        if ((unsigned)ny < GG && (unsigned)nx < GG)
            v = g_stoken[(b * NT + ny * GG + nx) * Cc + c];
        st9[idx] = v;
    }
    // load pixel block [p][c] with stride 257
    const float* xb = x + (size_t)b * Cc * HW + (ty * 8) * 128 + tx * 8;
    for (int idx = tid; idx < NP * Cc; idx += 256) {
        int c = idx >> 6;
        int p = idx & 63;
        int sy = p >> 3, sx = p & 7;
        pix_s[p * 257 + c] = xb[(size_t)c * HW + sy * 128 + sx];
    }
    __syncthreads();

    // partial dot products: thread (p, quarter q) over c in [q*64, q*64+64)
    {
        int p = tid & 63, q = tid >> 6;
        float acc[9];
#pragma unroll
        for (int k = 0; k < 9; k++) acc[k] = 0.f;
        const float* pr = pix_s + p * 257 + q * 64;
        const float* sr = st9 + q * 64;
        for (int cc = 0; cc < 64; cc++) {
            float pv = pr[cc];
#pragma unroll
            for (int k = 0; k < 9; k++) acc[k] += pv * sr[k * 256 + cc];
        }
#pragma unroll
        for (int k = 0; k < 9; k++) pd[(q * 64 + p) * 9 + k] = acc[k];
    }
    __syncthreads();
    // reduce 4 partials + scale
    for (int idx = tid; idx < 576; idx += 256) {
        float s = pd[idx] + pd[576 + idx] + pd[1152 + idx] + pd[1728 + idx];
        aff_s[idx] = s * AFF_SCALE;
    }
    __syncthreads();
    // softmax over k per pixel
    if (tid < 64) {
        float v[9];
        float mx = -1e30f;
#pragma unroll
        for (int k = 0; k < 9; k++) { v[k] = aff_s[tid * 9 + k]; mx = fmaxf(mx, v[k]); }
        float sum = 0.f;
#pragma unroll
        for (int k = 0; k < 9; k++) { v[k] = __expf(v[k] - mx); sum += v[k]; }
        float inv = 1.f / sum;
#pragma unroll
        for (int k = 0; k < 9; k++) aff_s[tid * 9 + k] = v[k] * inv;
    }
    __syncthreads();
    // store aff + asum_tok
    for (int idx = tid; idx < 576; idx += 256) g_aff[bt * 576 + idx] = aff_s[idx];
    if (tid < 9) {
        float s = 0.f;
        for (int p = 0; p < 64; p++) s += aff_s[p * 9 + tid];
        g_asum[bt * 9 + tid] = s;
    }
    // token GEMM: M[k][c] = sum_p pix[p][c]*aff[p][k]  (thread = c)
    {
        int c = tid;
        float acc[9];
#pragma unroll
        for (int k = 0; k < 9; k++) acc[k] = 0.f;
        for (int p = 0; p < 64; p++) {
            float pv = pix_s[p * 257 + c];
#pragma unroll
            for (int k = 0; k < 9; k++) acc[k] += pv * aff_s[p * 9 + k];
        }
        float* Mo = g_M + (size_t)bt * 9 * Cc;
#pragma unroll
        for (int k = 0; k < 9; k++) Mo[k * Cc + c] = acc[k];
    }
}

// ------------------------------- K3: fold ----------------------------------
__global__ void k_fold() {
    int bt = blockIdx.x;
    int b = bt >> 8, t = bt & 255;
    int y = t >> 4, x = t & 15;
    __shared__ float s_as;
    int tid = threadIdx.x;
    if (tid == 0) {
        float s = 0.f;
        for (int ny = y - 1; ny <= y + 1; ny++)
            for (int nx = x - 1; nx <= x + 1; nx++)
                if ((unsigned)ny < GG && (unsigned)nx < GG) {
                    int k = (y - ny + 1) * 3 + (x - nx + 1);
                    s += g_asum[(b * NT + ny * GG + nx) * 9 + k];
                }
        s_as = s + 1e-12f;
    }
    __syncthreads();
    int c = tid;
    float s = 0.f;
    for (int ny = y - 1; ny <= y + 1; ny++)
        for (int nx = x - 1; nx <= x + 1; nx++)
            if ((unsigned)ny < GG && (unsigned)nx < GG) {
                int k = (y - ny + 1) * 3 + (x - nx + 1);
                s += g_M[((size_t)(b * NT + ny * GG + nx) * 9 + k) * Cc + c];
            }
    g_sf[bt * Cc + c] = s / s_as;
}

// ------------------------------- GEMM (NT) ---------------------------------
// C = A(MMxKK, row-major) * Bm(b, NNxKK row-major)^T.
// TOUT=false: C[b][m][n]; TOUT=true: C[b][n][m].
template <int MM, int NN, int KK, bool TOUT>
__device__ __forceinline__ void gemm_body(const float* __restrict__ A,
                                          const float* __restrict__ Bm,
                                          float* __restrict__ Cm) {
    __shared__ float As[64][33];
    __shared__ float Bs[64][33];
    int bm = blockIdx.x * 64;
    int bn = blockIdx.y * 64;
    int b = blockIdx.z;
    const float* Bp = Bm + (size_t)b * NN * KK;
    int tid = threadIdx.x;
    int txq = tid & 15, tyq = tid >> 4;
    float acc[4][4];
#pragma unroll
    for (int i = 0; i < 4; i++)
#pragma unroll
        for (int j = 0; j < 4; j++) acc[i][j] = 0.f;

    for (int k0 = 0; k0 < KK; k0 += 32) {
        for (int idx = tid; idx < 64 * 32; idx += 256) {
            int r = idx >> 5, kk = idx & 31;
            As[r][kk] = A[(size_t)(bm + r) * KK + k0 + kk];
            Bs[r][kk] = Bp[(size_t)(bn + r) * KK + k0 + kk];
        }
        __syncthreads();
#pragma unroll
        for (int kk = 0; kk < 32; kk++) {
            float a[4], bb[4];
#pragma unroll
            for (int i = 0; i < 4; i++) a[i] = As[tyq * 4 + i][kk];
#pragma unroll
            for (int j = 0; j < 4; j++) bb[j] = Bs[txq * 4 + j][kk];
#pragma unroll
            for (int i = 0; i < 4; i++)
#pragma unroll
                for (int j = 0; j < 4; j++) acc[i][j] += a[i] * bb[j];
        }
        __syncthreads();
    }
    if (TOUT) {
        float* Cp = Cm + (size_t)b * NN * MM;
#pragma unroll
        for (int j = 0; j < 4; j++)
#pragma unroll
            for (int i = 0; i < 4; i++)
                Cp[(size_t)(bn + txq * 4 + j) * MM + bm + tyq * 4 + i] = acc[i][j];
    } else {
        float* Cp = Cm + (size_t)b * MM * NN;
#pragma unroll
        for (int i = 0; i < 4; i++)
#pragma unroll
            for (int j = 0; j < 4; j++)
                Cp[(size_t)(bm + tyq * 4 + i) * NN + bn + txq * 4 + j] = acc[i][j];
    }
}

__global__ void k_gemm_qkv(const float* __restrict__ A) {
    gemm_body<768, 256, 256, false>(A, g_sf, g_qkv);
}
__global__ void k_gemm_proj(const float* __restrict__ A) {
    gemm_body<256, 256, 256, true>(A, g_tmp, g_sfa);
}

// ------------------------------ K5: attention -------------------------------
// grid = 256 blocks: b (3b) | h (3b) | query-chunk (2b). 256 threads:
// thread = (j_local<<2) | dq, dq = d-quarter (8 dims each). Online softmax,
// score reduced across the 4-lane group via shfl. Depthwise 3x3 PE fused.
#define K5_KS (32 * 257)
#define K5_SMEM ((2 * K5_KS + 288) * 4)

__global__ void k_attn(const float* __restrict__ w_pe) {
    extern __shared__ float sm5[];
    float* k_s = sm5;
    float* v_s = k_s + K5_KS;
    float* wpe = v_s + K5_KS;

    int bx = blockIdx.x;
    int b = bx >> 5;
    int h = (bx >> 2) & 7;
    int jc = bx & 3;
    int tid = threadIdx.x;

    const float* qkv_b = g_qkv + ((size_t)b * 768 + h * 96) * NT;
    for (int idx = tid; idx < 32 * 256; idx += 256) {
        int d = idx >> 8, m = idx & 255;
        k_s[d * 257 + m] = qkv_b[32 * 256 + idx];
        v_s[d * 257 + m] = qkv_b[64 * 256 + idx];
    }
    for (int idx = tid; idx < 288; idx += 256) wpe[idx] = w_pe[h * 288 + idx];
    __syncthreads();

    int j = jc * 64 + (tid >> 2);
    int dq = tid & 3;
    float qd[8];
#pragma unroll
    for (int dd = 0; dd < 8; dd++)
        qd[dd] = qkv_b[(dq * 8 + dd) * 256 + j] * ATTN_SCALE;

    float o[8];
#pragma unroll
    for (int dd = 0; dd < 8; dd++) o[dd] = 0.f;
    float mx = -1e30f, l = 0.f;

    for (int m = 0; m < 256; m++) {
        float s = 0.f;
#pragma unroll
        for (int dd = 0; dd < 8; dd++) s += qd[dd] * k_s[(dq * 8 + dd) * 257 + m];
        s += __shfl_xor_sync(0xffffffffu, s, 1);
        s += __shfl_xor_sync(0xffffffffu, s, 2);
        float mn = fmaxf(mx, s);
        float corr = __expf(mx - mn);
        float p = __expf(s - mn);
        l = l * corr + p;
#pragma unroll
        for (int dd = 0; dd < 8; dd++)
            o[dd] = o[dd] * corr + p * v_s[(dq * 8 + dd) * 257 + m];
        mx = mn;
    }
    float invl = 1.f / l;

    int y = j >> 4, xx = j & 15;
    float* outp = g_tmp + ((size_t)(b * NT + j)) * Cc + h * 32 + dq * 8;
#pragma unroll
    for (int dd = 0; dd < 8; dd++) {
        float pe = 0.f;
#pragma unroll
        for (int u = 0; u < 3; u++) {
            int ny = y + u - 1;
            if ((unsigned)ny >= GG) continue;
#pragma unroll
            for (int v = 0; v < 3; v++) {
                int nx = xx + v - 1;
                if ((unsigned)nx >= GG) continue;
                pe += wpe[(dq * 8 + dd) * 9 + u * 3 + v] * v_s[(dq * 8 + dd) * 257 + ny * 16 + nx];
            }
        }
        outp[dd] = o[dd] * invl + pe;
    }
}

// ------------------------------ K7: scatter ---------------------------------
// out[b, c, token pixel s] = sum_k aff[p'][k] * sfa9[k][c'], where the
// reference's (p,C)->(C,SH,SW) reshape gives p' = c>>2, c' = (c&3)*64 + s.
__global__ void k_scatter(float* __restrict__ out) {
    __shared__ float s9[9 * 256];     // [k][c']
    __shared__ float aff_s[576];      // [p][k]
    int bt = blockIdx.x;
    int b = bt >> 8, t = bt & 255;
    int ty = t >> 4, tx = t & 15;
    int tid = threadIdx.x;

    for (int idx = tid; idx < 9 * 256; idx += 256) {
        int k = idx >> 8, c = idx & 255;
        int ny = ty + k / 3 - 1, nx = tx + k % 3 - 1;
        s9[idx] = ((unsigned)ny < GG && (unsigned)nx < GG)
                      ? g_sfa[(size_t)(b * NT + ny * GG + nx) * Cc + c]
                      : 0.f;
    }
    for (int idx = tid; idx < 576; idx += 256) aff_s[idx] = g_aff[bt * 576 + idx];
    __syncthreads();

    int s = tid & 63, q = tid >> 6;     // s = in-token pixel, q = channel quarter
    int sy = s >> 3, sx = s & 7;
    float* op = out + (size_t)b * Cc * HW + (ty * 8 + sy) * 128 + tx * 8 + sx;
    for (int c = q * 64; c < q * 64 + 64; c++) {
        int pprime = c >> 2;
        int cprime = ((c & 3) << 6) + s;
        const float* ar = aff_s + pprime * 9;
        float v = 0.f;
#pragma unroll
        for (int k = 0; k < 9; k++) v += ar[k] * s9[k * 256 + cprime];
        op[(size_t)c * HW] = v;
    }
}

// ------------------------------- launcher -----------------------------------
extern "C" void kernel_launch(void* const* d_in, const int* in_sizes, int n_in,
                              void* d_out, int out_size) {
    (void)in_sizes; (void)n_in; (void)out_size;
    const float* x      = (const float*)d_in[0];
    const float* w_qkv  = (const float*)d_in[1];
    const float* w_pe   = (const float*)d_in[2];
    const float* w_proj = (const float*)d_in[3];
    float* out = (float*)d_out;

    cudaFuncSetAttribute(k_aff, cudaFuncAttributeMaxDynamicSharedMemorySize, K2_SMEM);
    cudaFuncSetAttribute(k_attn, cudaFuncAttributeMaxDynamicSharedMemorySize, K5_SMEM);

    k_pool<<<Bb * NT, 256>>>(x);
    k_aff<<<Bb * NT, 256, K2_SMEM>>>(x);
    k_fold<<<Bb * NT, 256>>>();
    k_gemm_qkv<<<dim3(12, 4, 8), 256>>>(w_qkv);
    k_attn<<<256, 256, K5_SMEM>>>(w_pe);
    k_gemm_proj<<<dim3(4, 4, 8), 256>>>(w_proj);
    k_scatter<<<Bb * NT, 256>>>(out);
}